// round 16
// baseline (speedup 1.0000x reference)
#include <cuda_runtime.h>

// B=16384, NUM_CARDS=64, NUM_WORDS=50, LEN_EMB=128, LEN_DENSE=128
#define NC 64
#define NW 50
#define D  128
#define NBA 8                // batches per CTA, leader kernel
#define NBC 4                // batches per CTA, cosine kernel (2 warps/batch)
#define EPS 1e-8f

// Static device scratch (allocation-free), rewritten every launch (deterministic).
__device__ float4 g_WT[32 * 128];        // transposed W, float4-of-d packed
__device__ float  g_leader[16384 * D];   // Linear outputs for all batches (8.4 MB)

__global__ void transpose_W_kernel(const float* __restrict__ W)
{
    const int j = blockIdx.x * blockDim.x + threadIdx.x;   // 0..4095
    const int k = j >> 7;          // d-chunk
    const int e = j & 127;         // output index
    g_WT[j] = reinterpret_cast<const float4*>(W)[e * 32 + k];
}

// ---------------------------------------------------------------------------
// Kernel A: argmax + gather + matvec -> g_leader.
// ---------------------------------------------------------------------------
__global__ __launch_bounds__(256, 4)
void leader_kernel(const float* __restrict__ img,   // [B, NC, D]
                   const float* __restrict__ y,     // [B, NC]
                   const float* __restrict__ bias)  // [D]
{
    const int b0   = blockIdx.x * NBA;
    const int tid  = threadIdx.x;       // 256 threads = 8 warps
    const int lane = tid & 31;
    const int warp = tid >> 5;

    __shared__ float s_x[NBA][D];
    __shared__ int   s_idx[NBA];

    // argmax over 64 cards: warp nb handles batch b0+nb (first-index ties)
    {
        const long yb = (long)(b0 + warp) * NC;
        float v0 = y[yb + lane];
        float v1 = y[yb + lane + 32];
        float best; int bi;
        if (v1 > v0) { best = v1; bi = lane + 32; }
        else         { best = v0; bi = lane; }
        #pragma unroll
        for (int off = 16; off; off >>= 1) {
            float ov = __shfl_down_sync(0xffffffffu, best, off);
            int   oi = __shfl_down_sync(0xffffffffu, bi,   off);
            if (ov > best || (ov == best && oi < bi)) { best = ov; bi = oi; }
        }
        if (lane == 0) s_idx[warp] = bi;
    }
    __syncthreads();

    // gather 8 selected image rows (2 rows per 256-thread sweep)
    {
        const int r = tid >> 7;
        const int e = tid & 127;
        #pragma unroll
        for (int s = 0; s < 4; s++) {
            const int nb = s * 2 + r;
            s_x[nb][e] = img[((long)(b0 + nb) * NC + s_idx[nb]) * D + e];
        }
    }
    __syncthreads();

    // matvec with coalesced transposed W; write straight to g_leader
    {
        const int e    = tid & 127;
        const int half = tid >> 7;          // batches 4*half .. 4*half+3
        const float4* x0 = reinterpret_cast<const float4*>(s_x[4*half+0]);
        const float4* x1 = reinterpret_cast<const float4*>(s_x[4*half+1]);
        const float4* x2 = reinterpret_cast<const float4*>(s_x[4*half+2]);
        const float4* x3 = reinterpret_cast<const float4*>(s_x[4*half+3]);
        float a0 = 0.f, a1 = 0.f, a2 = 0.f, a3 = 0.f;
        #pragma unroll
        for (int k = 0; k < 32; k++) {
            const float4 w = g_WT[k * 128 + e];
            float4 v;
            v = x0[k]; a0 += w.x*v.x + w.y*v.y + w.z*v.z + w.w*v.w;
            v = x1[k]; a1 += w.x*v.x + w.y*v.y + w.z*v.z + w.w*v.w;
            v = x2[k]; a2 += w.x*v.x + w.y*v.y + w.z*v.z + w.w*v.w;
            v = x3[k]; a3 += w.x*v.x + w.y*v.y + w.z*v.z + w.w*v.w;
        }
        const float bv = __ldg(&bias[e]);
        g_leader[(long)(b0 + 4*half + 0) * D + e] = a0 + bv;   // coalesced
        g_leader[(long)(b0 + 4*half + 1) * D + e] = a1 + bv;
        g_leader[(long)(b0 + 4*half + 2) * D + e] = a2 + bv;
        g_leader[(long)(b0 + 4*half + 3) * D + e] = a3 + bv;
    }
}

// ---------------------------------------------------------------------------
// Kernel B: streaming cosine + softmax. 2 warps per batch (even/odd iters)
// -> per-warp duration halves (smaller tail drain); occupancy 5 CTAs/SM.
// ---------------------------------------------------------------------------
__global__ __launch_bounds__(256, 5)
void cosine_kernel(const float* __restrict__ txt,   // [B, NW, D]
                   float* __restrict__ out)         // [B, NW]
{
    const int tid  = threadIdx.x;
    const int lane = tid & 31;
    const int warp = tid >> 5;
    const int pair = warp >> 1;            // batch slot 0..3
    const int half = warp & 1;             // even/odd iteration half
    const int bb   = blockIdx.x * NBC + pair;

    __shared__ float s_logit[NBC][NW];

    const int sub = lane >> 3;     // word slot within group of 4
    const int sl  = lane & 7;      // position within word

    // leader float4s (L2-resident; second warp of each pair hits L1)
    const float4* ld4 = reinterpret_cast<const float4*>(g_leader + (long)bb * D);
    const float4 L0 = ld4[sl], L1 = ld4[sl + 8], L2 = ld4[sl + 16], L3 = ld4[sl + 24];

    // ||leader||: each 8-lane group collectively holds all 128 elements
    float na;
    {
        float sq = L0.x*L0.x + L0.y*L0.y + L0.z*L0.z + L0.w*L0.w
                 + L1.x*L1.x + L1.y*L1.y + L1.z*L1.z + L1.w*L1.w
                 + L2.x*L2.x + L2.y*L2.y + L2.z*L2.z + L2.w*L2.w
                 + L3.x*L3.x + L3.y*L3.y + L3.z*L3.z + L3.w*L3.w;
        #pragma unroll
        for (int off = 4; off; off >>= 1)
            sq += __shfl_xor_sync(0xffffffffu, sq, off, 8);
        na = sqrtf(sq);
    }

    const float4* t4 = reinterpret_cast<const float4*>(txt + (long)bb * NW * D);

    #pragma unroll
    for (int i = 0; i < 7; i++) {               // wi = 2i+half covers 0..12
        const int wi = 2 * i + half;
        if (wi >= 13) break;                    // half=1, i=6 only
        const int word  = wi * 4 + sub;
        const int aw    = word < NW ? word : NW - 1;   // clamp reads, mask store
        const float4* p = t4 + aw * 32 + sl;
        float4 a = __ldcs(p);                   // 4 loads in flight (MLP=4)
        float4 b = __ldcs(p + 8);
        float4 c = __ldcs(p + 16);
        float4 e = __ldcs(p + 24);
        float d = a.x*L0.x + a.y*L0.y + a.z*L0.z + a.w*L0.w
                + b.x*L1.x + b.y*L1.y + b.z*L1.z + b.w*L1.w
                + c.x*L2.x + c.y*L2.y + c.z*L2.z + c.w*L2.w
                + e.x*L3.x + e.y*L3.y + e.z*L3.z + e.w*L3.w;
        float n = a.x*a.x + a.y*a.y + a.z*a.z + a.w*a.w
                + b.x*b.x + b.y*b.y + b.z*b.z + b.w*b.w
                + c.x*c.x + c.y*c.y + c.z*c.z + c.w*c.w
                + e.x*e.x + e.y*e.y + e.z*e.z + e.w*e.w;
        #pragma unroll
        for (int off = 4; off; off >>= 1) {     // 3 rounds over 8 lanes
            d += __shfl_down_sync(0xffffffffu, d, off, 8);
            n += __shfl_down_sync(0xffffffffu, n, off, 8);
        }
        if (sl == 0 && word < NW)
            s_logit[pair][word] = d / fmaxf(na * sqrtf(n), EPS);
    }
    __syncthreads();

    // softmax over 50 words: warps 0-3, one batch each
    if (warp < NBC) {
        float v0 = s_logit[warp][lane];
        float v1 = (lane + 32 < NW) ? s_logit[warp][lane + 32] : -1e30f;
        float m = fmaxf(v0, v1);
        #pragma unroll
        for (int off = 16; off; off >>= 1)
            m = fmaxf(m, __shfl_xor_sync(0xffffffffu, m, off));
        float e0 = __expf(v0 - m);
        float e1 = (lane + 32 < NW) ? __expf(v1 - m) : 0.f;
        float s = e0 + e1;
        #pragma unroll
        for (int off = 16; off; off >>= 1)
            s += __shfl_xor_sync(0xffffffffu, s, off);
        const float inv = 1.0f / s;
        float* o = out + (long)(blockIdx.x * NBC + warp) * NW;
        o[lane] = e0 * inv;
        if (lane + 32 < NW) o[lane + 32] = e1 * inv;
    }
}

extern "C" void kernel_launch(void* const* d_in, const int* in_sizes, int n_in,
                              void* d_out, int out_size)
{
    const float* img  = (const float*)d_in[0];   // [B, 64, 128]
    const float* txt  = (const float*)d_in[1];   // [B, 50, 128]
    const float* yy   = (const float*)d_in[2];   // [B, 64]
    const float* W    = (const float*)d_in[3];   // [128, 128]
    const float* bias = (const float*)d_in[4];   // [128]
    float* out = (float*)d_out;                  // [B, 50]

    const int B = in_sizes[2] / NC;              // 16384

    // Same stream: ordered transpose -> leaders -> streaming cosine/softmax.
    transpose_W_kernel<<<64, 64>>>(W);
    leader_kernel<<<B / NBA, 256>>>(img, yy, bias);
    cosine_kernel<<<B / NBC, 256>>>(txt, out);
}

// round 17
// speedup vs baseline: 1.0430x; 1.0430x over previous
#include <cuda_runtime.h>

// B=16384, NUM_CARDS=64, NUM_WORDS=50, LEN_EMB=128, LEN_DENSE=128
#define NC 64
#define NW 50
#define D  128
#define NB 8                 // batch rows per CTA (8 warps, warp-per-batch)
#define EPS 1e-8f

// Transposed, float4-of-d packed W: WT[k][e] = float4(W[e][4k..4k+4)), k<32, e<128.
// 64 KB static scratch (allocation-free), rewritten every launch (deterministic).
__device__ float4 g_WT[32 * 128];

__global__ void transpose_W_kernel(const float* __restrict__ W)
{
    const int j = blockIdx.x * blockDim.x + threadIdx.x;   // 0..4095
    const int k = j >> 7;          // d-chunk
    const int e = j & 127;         // output index
    g_WT[j] = reinterpret_cast<const float4*>(W)[e * 32 + k];
}

__global__ __launch_bounds__(256, 4)   // 4 CTAs x 8 warps = 32 warps/SM, 64-reg budget
void imaginarium_kernel(const float* __restrict__ img,   // [B, NC, D]
                        const float* __restrict__ txt,   // [B, NW, D]
                        const float* __restrict__ y,     // [B, NC]
                        const float* __restrict__ bias,  // [D]
                        float* __restrict__ out)         // [B, NW]
{
    const int b0   = blockIdx.x * NB;
    const int tid  = threadIdx.x;       // 256 threads = 8 warps
    const int lane = tid & 31;
    const int warp = tid >> 5;          // warp nb owns batch b0+nb

    __shared__ float s_x[NB][D];        // selected image rows
    __shared__ float s_leader[NB][D];   // Linear outputs
    __shared__ float s_logit[NB][NW];
    __shared__ int   s_idx[NB];

    // ---- 1) argmax over 64 cards: warp nb handles batch b0+nb ----
    {
        const long yb = (long)(b0 + warp) * NC;
        float v0 = y[yb + lane];
        float v1 = y[yb + lane + 32];
        float best; int bi;
        if (v1 > v0) { best = v1; bi = lane + 32; }   // tie -> lower index
        else         { best = v0; bi = lane; }
        #pragma unroll
        for (int off = 16; off; off >>= 1) {
            float ov = __shfl_down_sync(0xffffffffu, best, off);
            int   oi = __shfl_down_sync(0xffffffffu, bi,   off);
            if (ov > best || (ov == best && oi < bi)) { best = ov; bi = oi; }
        }
        if (lane == 0) s_idx[warp] = bi;
    }
    __syncthreads();

    // ---- 2) gather NB selected image rows (2 rows per 256-thread sweep) ----
    {
        const int r  = tid >> 7;
        const int e  = tid & 127;
        #pragma unroll
        for (int s = 0; s < 4; s++) {
            const int nb = s * 2 + r;
            s_x[nb][e] = img[((long)(b0 + nb) * NC + s_idx[nb]) * D + e];
        }
    }
    __syncthreads();

    // ---- 3) matvec with coalesced transposed W ----
    {
        const int e    = tid & 127;
        const int half = tid >> 7;          // batches 4*half .. 4*half+3
        const float4* x0 = reinterpret_cast<const float4*>(s_x[4*half+0]);
        const float4* x1 = reinterpret_cast<const float4*>(s_x[4*half+1]);
        const float4* x2 = reinterpret_cast<const float4*>(s_x[4*half+2]);
        const float4* x3 = reinterpret_cast<const float4*>(s_x[4*half+3]);
        float a0 = 0.f, a1 = 0.f, a2 = 0.f, a3 = 0.f;
        #pragma unroll
        for (int k = 0; k < 32; k++) {
            const float4 w = g_WT[k * 128 + e];   // coalesced, L1/L2-resident
            float4 v;
            v = x0[k]; a0 += w.x*v.x + w.y*v.y + w.z*v.z + w.w*v.w;
            v = x1[k]; a1 += w.x*v.x + w.y*v.y + w.z*v.z + w.w*v.w;
            v = x2[k]; a2 += w.x*v.x + w.y*v.y + w.z*v.z + w.w*v.w;
            v = x3[k]; a3 += w.x*v.x + w.y*v.y + w.z*v.z + w.w*v.w;
        }
        const float bv = __ldg(&bias[e]);
        s_leader[4*half+0][e] = a0 + bv;
        s_leader[4*half+1][e] = a1 + bv;
        s_leader[4*half+2][e] = a2 + bv;
        s_leader[4*half+3][e] = a3 + bv;
    }
    __syncthreads();

    // ---- 4+5) per-warp: ||leader||, then PIPELINED cosine similarity ----
    {
        const int  bb  = b0 + warp;
        const int  sub = lane >> 3;     // word slot within group of 4
        const int  sl  = lane & 7;      // position within word
        const float4* ld4 = reinterpret_cast<const float4*>(s_leader[warp]);

        // ||leader||^2: xor-reduce so every lane holds na
        float na;
        {
            const float4 v = ld4[lane];
            float sq = v.x*v.x + v.y*v.y + v.z*v.z + v.w*v.w;
            #pragma unroll
            for (int off = 16; off; off >>= 1)
                sq += __shfl_xor_sync(0xffffffffu, sq, off);
            na = sqrtf(sq);
        }

        const float4* t4 = reinterpret_cast<const float4*>(txt + (long)bb * NW * D);
        const float4 L0 = ld4[sl], L1 = ld4[sl + 8], L2 = ld4[sl + 16], L3 = ld4[sl + 24];

        // prologue: loads for wi=0 (word = sub < 50 always)
        const float4* p0 = t4 + sub * 32 + sl;
        float4 a = __ldcs(p0);
        float4 b = __ldcs(p0 + 8);
        float4 c = __ldcs(p0 + 16);
        float4 e = __ldcs(p0 + 24);

        #pragma unroll
        for (int wi = 0; wi < 13; wi++) {        // 13*4 = 52 slots, 2 masked
            // issue NEXT iteration's loads before consuming current regs:
            // gives each load a full iteration of slack (MLP ~8 per warp).
            float4 a2, b2, c2, e2;
            if (wi < 12) {
                const int wn  = (wi + 1) * 4 + sub;
                const int awn = wn < NW ? wn : NW - 1;
                const float4* pn = t4 + awn * 32 + sl;
                a2 = __ldcs(pn);
                b2 = __ldcs(pn + 8);
                c2 = __ldcs(pn + 16);
                e2 = __ldcs(pn + 24);
            }

            float d = a.x*L0.x + a.y*L0.y + a.z*L0.z + a.w*L0.w
                    + b.x*L1.x + b.y*L1.y + b.z*L1.z + b.w*L1.w
                    + c.x*L2.x + c.y*L2.y + c.z*L2.z + c.w*L2.w
                    + e.x*L3.x + e.y*L3.y + e.z*L3.z + e.w*L3.w;
            float n = a.x*a.x + a.y*a.y + a.z*a.z + a.w*a.w
                    + b.x*b.x + b.y*b.y + b.z*b.z + b.w*b.w
                    + c.x*c.x + c.y*c.y + c.z*c.z + c.w*c.w
                    + e.x*e.x + e.y*e.y + e.z*e.z + e.w*e.w;
            #pragma unroll
            for (int off = 4; off; off >>= 1) {  // 3 rounds over 8 lanes
                d += __shfl_down_sync(0xffffffffu, d, off, 8);
                n += __shfl_down_sync(0xffffffffu, n, off, 8);
            }
            const int word = wi * 4 + sub;
            if (sl == 0 && word < NW)
                s_logit[warp][word] = d / fmaxf(na * sqrtf(n), EPS);

            a = a2; b = b2; c = c2; e = e2;      // rotate buffers
        }
        __syncwarp();

        // ---- 6) softmax over 50 words (per warp, own batch) ----
        float v0 = s_logit[warp][lane];
        float v1 = (lane + 32 < NW) ? s_logit[warp][lane + 32] : -1e30f;
        float m = fmaxf(v0, v1);
        #pragma unroll
        for (int off = 16; off; off >>= 1)
            m = fmaxf(m, __shfl_xor_sync(0xffffffffu, m, off));
        float e0 = __expf(v0 - m);
        float e1 = (lane + 32 < NW) ? __expf(v1 - m) : 0.f;
        float s = e0 + e1;
        #pragma unroll
        for (int off = 16; off; off >>= 1)
            s += __shfl_xor_sync(0xffffffffu, s, off);
        const float inv = 1.0f / s;
        float* o = out + (long)bb * NW;
        o[lane] = e0 * inv;
        if (lane + 32 < NW) o[lane + 32] = e1 * inv;
    }
}

extern "C" void kernel_launch(void* const* d_in, const int* in_sizes, int n_in,
                              void* d_out, int out_size)
{
    const float* img  = (const float*)d_in[0];   // [B, 64, 128]
    const float* txt  = (const float*)d_in[1];   // [B, 50, 128]
    const float* yy   = (const float*)d_in[2];   // [B, 64]
    const float* W    = (const float*)d_in[3];   // [128, 128]
    const float* bias = (const float*)d_in[4];   // [128]
    float* out = (float*)d_out;                  // [B, 50]

    const int B = in_sizes[2] / NC;              // 16384, divisible by NB

    // Prologue: pack W into transposed float4-of-d layout (same stream ->
    // ordered before the main kernel; both launches are capture-safe).
    transpose_W_kernel<<<16, 256>>>(W);
    imaginarium_kernel<<<B / NB, 256>>>(img, txt, yy, bias, out);
}